// round 10
// baseline (speedup 1.0000x reference)
#include <cuda_runtime.h>
#include <cuda_fp16.h>
#include <cstdint>

// ---------------------------------------------------------------------------
// GraphConvolution: out = segment_sum( (X@W)[edge_src] * edge_val, edge_dst )
// Stage 0: W f32 [k][n] -> fp16 transposed [n][k]
// Stage 1: GEMM mma.sync fp16, BM=64/128thr, cp.async f32 A + fused convert
// Stage 2: rowptr via binary search (edge_dst sorted)
// Stage 3: warp-per-node segment sum, fp16 gathers, unroll 8
// ---------------------------------------------------------------------------

#define MAX_NODES 50000
#define D_IN      512
#define D_OUT     128
#define BM        64
#define BK        32
#define NSTEP     (D_IN / BK)   // 16
#define STAGES    3

// dynamic smem layout (bytes):
//   [0, 24576)        A f32 slots: 3 x 8192  (64 rows x 128B)
//   [24576, 49152)    B f16 slots: 3 x 8192  (128 rows x 64B)
//   [49152, 57344)    A f16 ping-pong: 2 x 4096 (64 rows x 64B)
#define OFF_AF32  0
#define OFF_BF16  24576
#define OFF_AF16  49152
#define SMEM_DYN  57344

__device__ __align__(16) __half g_support_h[(size_t)MAX_NODES * D_OUT];
__device__ int   g_rowptr[MAX_NODES + 1];
__device__ __align__(16) __half g_Wh[D_OUT * D_IN];            // [n][k]

// ------------------------------- helpers -----------------------------------
__device__ __forceinline__ uint32_t smem_u32(const void* p) {
    uint32_t a;
    asm("{ .reg .u64 t; cvta.to.shared.u64 t, %1; cvt.u32.u64 %0, t; }"
        : "=r"(a) : "l"(p));
    return a;
}
// 64B-row swizzle (fp16 tiles): 16B chunk idx ^= (row>>1)&3
__device__ __forceinline__ uint32_t swz64(uint32_t r, uint32_t c) {
    return r * 64 + ((((c >> 4) ^ (r >> 1)) & 3u) << 4) + (c & 15u);
}
// 128B-row swizzle (f32 tiles): 16B chunk idx ^= row&7
__device__ __forceinline__ uint32_t swzf32(uint32_t r, uint32_t c) {
    return r * 128 + ((((c >> 4) ^ r) & 7u) << 4) + (c & 15u);
}

#define CP_ASYNC16(dst, src) \
    asm volatile("cp.async.cg.shared.global [%0], [%1], 16;" \
        :: "r"(dst), "l"(src) : "memory")
#define CP_COMMIT() asm volatile("cp.async.commit_group;" ::: "memory")
#define CP_WAIT1()  asm volatile("cp.async.wait_group 1;" ::: "memory")
#define CP_WAIT2()  asm volatile("cp.async.wait_group 2;" ::: "memory")

#define LDSM4(r0, r1, r2, r3, a) \
    asm volatile("ldmatrix.sync.aligned.m8n8.x4.shared.b16 {%0,%1,%2,%3}, [%4];" \
        : "=r"(r0), "=r"(r1), "=r"(r2), "=r"(r3) : "r"(a))
#define LDSM2(r0, r1, a) \
    asm volatile("ldmatrix.sync.aligned.m8n8.x2.shared.b16 {%0,%1}, [%2];" \
        : "=r"(r0), "=r"(r1) : "r"(a))
#define MMA16816F16(c, a, b) \
    asm volatile("mma.sync.aligned.m16n8k16.row.col.f32.f16.f16.f32 " \
        "{%0,%1,%2,%3}, {%4,%5,%6,%7}, {%8,%9}, {%0,%1,%2,%3};" \
        : "+f"((c)[0]), "+f"((c)[1]), "+f"((c)[2]), "+f"((c)[3]) \
        : "r"((a)[0]), "r"((a)[1]), "r"((a)[2]), "r"((a)[3]), \
          "r"((b)[0]), "r"((b)[1]))

__device__ __forceinline__ uint32_t pack_h2(float lo, float hi) {
    __half2 h = __float22half2_rn(make_float2(lo, hi));
    return *reinterpret_cast<uint32_t*>(&h);
}

// ---------------------------------------------------------------------------
// Stage 0: convert + transpose W -> fp16 [n][k]
// ---------------------------------------------------------------------------
__global__ void convw_kernel(const float* __restrict__ W)
{
    int idx = blockIdx.x * blockDim.x + threadIdx.x;
    if (idx >= D_IN * D_OUT) return;
    int k = idx >> 7;
    int n = idx & 127;
    g_Wh[n * D_IN + k] = __float2half_rn(W[idx]);
}

// ---------------------------------------------------------------------------
// Stage 1: GEMM; 64x128 tile, 128 threads (4 warps, each 64x32 slice)
// ---------------------------------------------------------------------------
__global__ __launch_bounds__(128, 4)
void gemm_mma_kernel(const float* __restrict__ X, int M)
{
    extern __shared__ char dyn[];
    const uint32_t sb = smem_u32(dyn);

    const int tid  = threadIdx.x;
    const int w    = tid >> 5;
    const int lane = tid & 31;
    const int gid  = lane >> 2;
    const int tig  = lane & 3;
    const int rowBase = blockIdx.x * BM;
    const int nBase = w * 32;

    float acc[4][4][4];
#pragma unroll
    for (int i = 0; i < 4; i++)
#pragma unroll
        for (int j = 0; j < 4; j++)
#pragma unroll
            for (int q = 0; q < 4; q++) acc[i][j][q] = 0.f;

    // A copy: row ar (0..63), byte-seg aseg (0 or 64); 4 x 16B chunks
    const int ar   = tid >> 1;
    const int aseg = (tid & 1) * 64;
    // B copy: row br = tid (0..127); 4 x 16B chunks (whole 64B row)
    const int br   = tid;
    const float*  xsrc = X + (size_t)(rowBase + ar < M ? rowBase + ar : M - 1) * D_IN;
    const __half* wsrc = g_Wh + (size_t)br * D_IN;

    auto issue_stage = [&](int s, int k0) {
        uint32_t aB = sb + OFF_AF32 + s * 8192;
        uint32_t bB = sb + OFF_BF16 + s * 8192;
#pragma unroll
        for (int j = 0; j < 4; j++) {
            int c = aseg + j * 16;
            CP_ASYNC16(aB + swzf32((uint32_t)ar, (uint32_t)c), xsrc + k0 + c / 4);
        }
#pragma unroll
        for (int j = 0; j < 4; j++) {
            CP_ASYNC16(bB + swz64((uint32_t)br, (uint32_t)(j * 16)), wsrc + k0 + j * 8);
        }
    };

    // convert A f32 slot s -> fp16 ping-pong p (16 floats/thread)
    auto convert_stage = [&](int s, int p) {
        const char* src = dyn + OFF_AF32 + s * 8192;
        char*       dst = dyn + OFF_AF16 + p * 4096;
        float4 f0 = *reinterpret_cast<const float4*>(src + swzf32((uint32_t)ar, (uint32_t)(aseg)));
        float4 f1 = *reinterpret_cast<const float4*>(src + swzf32((uint32_t)ar, (uint32_t)(aseg + 16)));
        float4 f2 = *reinterpret_cast<const float4*>(src + swzf32((uint32_t)ar, (uint32_t)(aseg + 32)));
        float4 f3 = *reinterpret_cast<const float4*>(src + swzf32((uint32_t)ar, (uint32_t)(aseg + 48)));
        uint4 h0 = make_uint4(pack_h2(f0.x, f0.y), pack_h2(f0.z, f0.w),
                              pack_h2(f1.x, f1.y), pack_h2(f1.z, f1.w));
        uint4 h1 = make_uint4(pack_h2(f2.x, f2.y), pack_h2(f2.z, f2.w),
                              pack_h2(f3.x, f3.y), pack_h2(f3.z, f3.w));
        *reinterpret_cast<uint4*>(dst + swz64((uint32_t)ar, (uint32_t)(aseg / 2)))      = h0;
        *reinterpret_cast<uint4*>(dst + swz64((uint32_t)ar, (uint32_t)(aseg / 2 + 16))) = h1;
    };

    // ---- prologue ----
    issue_stage(0, 0);       CP_COMMIT();
    issue_stage(1, BK);      CP_COMMIT();
    issue_stage(2, 2 * BK);  CP_COMMIT();
    CP_WAIT2();
    __syncthreads();
    convert_stage(0, 0);
    __syncthreads();

    for (int i = 0; i < NSTEP; i++) {
        const int cur = i % 3;
        const int pp  = i & 1;

        if (i + 1 < NSTEP) {
            CP_WAIT1();
            __syncthreads();
            convert_stage((i + 1) % 3, pp ^ 1);
        }

        const uint32_t aBase = sb + OFF_AF16 + pp * 4096;
        const uint32_t bBase = sb + OFF_BF16 + cur * 8192;
#pragma unroll
        for (int s = 0; s < 2; s++) {
            uint32_t af[4][4], bf[4][2];
#pragma unroll
            for (int mf = 0; mf < 4; mf++) {
                uint32_t a = aBase + swz64((uint32_t)(mf * 16 + (lane & 15)),
                                           (uint32_t)(s * 32 + ((lane >> 4) & 1) * 16));
                LDSM4(af[mf][0], af[mf][1], af[mf][2], af[mf][3], a);
            }
#pragma unroll
            for (int nf = 0; nf < 4; nf++) {
                uint32_t b = bBase + swz64((uint32_t)(nBase + nf * 8 + (lane & 7)),
                                           (uint32_t)(s * 32 + ((lane >> 3) & 1) * 16));
                LDSM2(bf[nf][0], bf[nf][1], b);
            }
#pragma unroll
            for (int mf = 0; mf < 4; mf++)
#pragma unroll
                for (int nf = 0; nf < 4; nf++)
                    MMA16816F16(acc[mf][nf], af[mf], bf[nf]);
        }
        __syncthreads();

        if (i + 3 < NSTEP)
            issue_stage(cur, (i + 3) * BK);
        CP_COMMIT();
    }

    // ---- epilogue: write support as fp16 ----
#pragma unroll
    for (int mf = 0; mf < 4; mf++) {
        int r0 = rowBase + mf * 16 + gid;
        int r1 = r0 + 8;
#pragma unroll
        for (int nf = 0; nf < 4; nf++) {
            int col = nBase + nf * 8 + tig * 2;
            if (r0 < M)
                *reinterpret_cast<uint32_t*>(&g_support_h[(size_t)r0 * D_OUT + col]) =
                    pack_h2(acc[mf][nf][0], acc[mf][nf][1]);
            if (r1 < M)
                *reinterpret_cast<uint32_t*>(&g_support_h[(size_t)r1 * D_OUT + col]) =
                    pack_h2(acc[mf][nf][2], acc[mf][nf][3]);
        }
    }
}

// ---------------------------------------------------------------------------
// Stage 2: rowptr[i] = lower_bound(edge_dst, i)
// ---------------------------------------------------------------------------
__global__ void rowptr_kernel(const int* __restrict__ edge_dst, int E, int M)
{
    int i = blockIdx.x * blockDim.x + threadIdx.x;
    if (i > M) return;
    int lo = 0, hi = E;
    while (lo < hi) {
        int mid = (lo + hi) >> 1;
        if (edge_dst[mid] < i) lo = mid + 1; else hi = mid;
    }
    g_rowptr[i] = lo;
}

// ---------------------------------------------------------------------------
// Stage 3: warp per node segment sum; fp16 gathers, unroll 8 (MLP=8)
// ---------------------------------------------------------------------------
__global__ __launch_bounds__(256)
void spmm_kernel(const int* __restrict__ edge_src,
                 const float* __restrict__ edge_val,
                 float* __restrict__ out, int M)
{
    const int warp = threadIdx.x >> 5;
    const int lane = threadIdx.x & 31;
    const int node = blockIdx.x * 8 + warp;
    if (node >= M) return;

    const int s = g_rowptr[node];
    const int e = g_rowptr[node + 1];

    float4 acc = make_float4(0.f, 0.f, 0.f, 0.f);
    float4 acc2 = make_float4(0.f, 0.f, 0.f, 0.f);
    const int col = lane * 4;
    const __half* supp = g_support_h;

    int i = s;
    for (; i + 7 < e; i += 8) {
        int   si[8]; float vi[8]; uint2 qi[8];
#pragma unroll
        for (int j = 0; j < 8; j++) si[j] = edge_src[i + j];
#pragma unroll
        for (int j = 0; j < 8; j++) vi[j] = edge_val[i + j];
#pragma unroll
        for (int j = 0; j < 8; j++)
            qi[j] = *reinterpret_cast<const uint2*>(&supp[(size_t)si[j] * D_OUT + col]);
#pragma unroll
        for (int j = 0; j < 8; j++) {
            float2 f0 = __half22float2(*reinterpret_cast<__half2*>(&qi[j].x));
            float2 f1 = __half22float2(*reinterpret_cast<__half2*>(&qi[j].y));
            if (j & 1) {
                acc2.x = fmaf(f0.x, vi[j], acc2.x); acc2.y = fmaf(f0.y, vi[j], acc2.y);
                acc2.z = fmaf(f1.x, vi[j], acc2.z); acc2.w = fmaf(f1.y, vi[j], acc2.w);
            } else {
                acc.x = fmaf(f0.x, vi[j], acc.x); acc.y = fmaf(f0.y, vi[j], acc.y);
                acc.z = fmaf(f1.x, vi[j], acc.z); acc.w = fmaf(f1.y, vi[j], acc.w);
            }
        }
    }
    for (; i < e; ++i) {
        int sr = edge_src[i];
        float v = edge_val[i];
        uint2 q = *reinterpret_cast<const uint2*>(&supp[(size_t)sr * D_OUT + col]);
        float2 f0 = __half22float2(*reinterpret_cast<__half2*>(&q.x));
        float2 f1 = __half22float2(*reinterpret_cast<__half2*>(&q.y));
        acc.x = fmaf(f0.x, v, acc.x); acc.y = fmaf(f0.y, v, acc.y);
        acc.z = fmaf(f1.x, v, acc.z); acc.w = fmaf(f1.y, v, acc.w);
    }
    acc.x += acc2.x; acc.y += acc2.y; acc.z += acc2.z; acc.w += acc2.w;

    *reinterpret_cast<float4*>(&out[(size_t)node * D_OUT + col]) = acc;
}

// ---------------------------------------------------------------------------
extern "C" void kernel_launch(void* const* d_in, const int* in_sizes, int n_in,
                              void* d_out, int out_size)
{
    const float* x        = (const float*)d_in[0];
    const int*   edge_src = (const int*)  d_in[1];
    const int*   edge_dst = (const int*)  d_in[2];
    const float* edge_val = (const float*)d_in[3];
    const float* weight   = (const float*)d_in[4];
    float*       out      = (float*)d_out;

    const int M = in_sizes[0] / D_IN;   // 50000
    const int E = in_sizes[1];          // 800000

    cudaFuncSetAttribute(gemm_mma_kernel,
                         cudaFuncAttributeMaxDynamicSharedMemorySize, SMEM_DYN);

    convw_kernel<<<(D_IN * D_OUT + 255) / 256, 256>>>(weight);
    rowptr_kernel<<<(M + 1 + 255) / 256, 256>>>(edge_dst, E, M);
    gemm_mma_kernel<<<(M + BM - 1) / BM, 128, SMEM_DYN>>>(x, M);
    spmm_kernel<<<(M + 7) / 8, 256>>>(edge_src, edge_val, out, M);
}

// round 11
// speedup vs baseline: 1.1158x; 1.1158x over previous
#include <cuda_runtime.h>
#include <cuda_fp16.h>
#include <cstdint>

// ---------------------------------------------------------------------------
// GraphConvolution: out = segment_sum( (X@W)[edge_src] * edge_val, edge_dst )
// Stage 0: W f32 [k][n] -> fp16 transposed [n][k]
// Stage 1: GEMM mma.sync fp16, BM=128/256thr.
//          A: direct LDG f32 -> reg cvt -> STS fp16 (3-slot ring, distance 2)
//          B: cp.async fp16 3-stage
// Stage 2: rowptr via binary search (edge_dst sorted)
// Stage 3: warp-per-node segment sum, fp16 gathers, unroll 8
// ---------------------------------------------------------------------------

#define MAX_NODES 50000
#define D_IN      512
#define D_OUT     128
#define BM        128
#define BK        32
#define NSTEP     (D_IN / BK)   // 16

// static smem: A fp16 ring 3 x 8192 + B fp16 ring 3 x 8192 = 48KB
__device__ __align__(16) __half g_support_h[(size_t)MAX_NODES * D_OUT];
__device__ int   g_rowptr[MAX_NODES + 1];
__device__ __align__(16) __half g_Wh[D_OUT * D_IN];            // [n][k]

// ------------------------------- helpers -----------------------------------
__device__ __forceinline__ uint32_t smem_u32(const void* p) {
    uint32_t a;
    asm("{ .reg .u64 t; cvta.to.shared.u64 t, %1; cvt.u32.u64 %0, t; }"
        : "=r"(a) : "l"(p));
    return a;
}
// 64B-row swizzle (fp16 tiles): 16B chunk idx ^= (row>>1)&3
__device__ __forceinline__ uint32_t swz64(uint32_t r, uint32_t c) {
    return r * 64 + ((((c >> 4) ^ (r >> 1)) & 3u) << 4) + (c & 15u);
}

#define CP_ASYNC16(dst, src) \
    asm volatile("cp.async.cg.shared.global [%0], [%1], 16;" \
        :: "r"(dst), "l"(src) : "memory")
#define CP_COMMIT() asm volatile("cp.async.commit_group;" ::: "memory")
#define CP_WAIT2()  asm volatile("cp.async.wait_group 2;" ::: "memory")

#define LDSM4(r0, r1, r2, r3, a) \
    asm volatile("ldmatrix.sync.aligned.m8n8.x4.shared.b16 {%0,%1,%2,%3}, [%4];" \
        : "=r"(r0), "=r"(r1), "=r"(r2), "=r"(r3) : "r"(a))
#define LDSM2(r0, r1, a) \
    asm volatile("ldmatrix.sync.aligned.m8n8.x2.shared.b16 {%0,%1}, [%2];" \
        : "=r"(r0), "=r"(r1) : "r"(a))
#define MMA16816F16(c, a, b) \
    asm volatile("mma.sync.aligned.m16n8k16.row.col.f32.f16.f16.f32 " \
        "{%0,%1,%2,%3}, {%4,%5,%6,%7}, {%8,%9}, {%0,%1,%2,%3};" \
        : "+f"((c)[0]), "+f"((c)[1]), "+f"((c)[2]), "+f"((c)[3]) \
        : "r"((a)[0]), "r"((a)[1]), "r"((a)[2]), "r"((a)[3]), \
          "r"((b)[0]), "r"((b)[1]))

__device__ __forceinline__ uint32_t pack_h2(float lo, float hi) {
    __half2 h = __float22half2_rn(make_float2(lo, hi));
    return *reinterpret_cast<uint32_t*>(&h);
}

// ---------------------------------------------------------------------------
// Stage 0: convert + transpose W -> fp16 [n][k]
// ---------------------------------------------------------------------------
__global__ void convw_kernel(const float* __restrict__ W)
{
    int idx = blockIdx.x * blockDim.x + threadIdx.x;
    if (idx >= D_IN * D_OUT) return;
    int k = idx >> 7;
    int n = idx & 127;
    g_Wh[n * D_IN + k] = __float2half_rn(W[idx]);
}

// ---------------------------------------------------------------------------
// Stage 1: GEMM; 128x128 tile, 256 threads (8 warps, each 64x32 slice)
// ---------------------------------------------------------------------------
__global__ __launch_bounds__(256, 2)
void gemm_mma_kernel(const float* __restrict__ X, int M)
{
    __shared__ __align__(128) char smA[3][8192];   // fp16 A ring
    __shared__ __align__(128) char smB[3][8192];   // fp16 B ring

    const int tid  = threadIdx.x;
    const int w    = tid >> 5;
    const int lane = tid & 31;
    const int gid  = lane >> 2;
    const int tig  = lane & 3;
    const int rowBase = blockIdx.x * BM;
    const int mBase = (w >> 2) * 64;
    const int nBase = (w & 3) * 32;

    float acc[4][4][4];
#pragma unroll
    for (int i = 0; i < 4; i++)
#pragma unroll
        for (int j = 0; j < 4; j++)
#pragma unroll
            for (int q = 0; q < 4; q++) acc[i][j][q] = 0.f;

    // A: thread -> row ar (0..127), half h (0/1): floats [h*16, h*16+16)
    const int ar = tid >> 1;
    const int ah = (tid & 1) * 16;            // float offset within 32
    // B: thread -> row br (0..127), 2 x 16B chunks at byte cols bc, bc+16
    const int bc = (tid & 1) * 32;
    const float*  xsrc = X + (size_t)(rowBase + ar < M ? rowBase + ar : M - 1) * D_IN;
    const __half* wsrc = g_Wh + (size_t)ar * D_IN;

    const uint32_t saBase = smem_u32(smA);
    const uint32_t sbBase = smem_u32(smB);

    auto issueB = [&](int s, int k0) {
        uint32_t bB = sbBase + s * 8192;
        CP_ASYNC16(bB + swz64((uint32_t)ar, (uint32_t)bc),        wsrc + k0 + bc / 2);
        CP_ASYNC16(bB + swz64((uint32_t)ar, (uint32_t)(bc + 16)), wsrc + k0 + bc / 2 + 8);
    };
    // direct LDG f32 -> cvt -> STS fp16 into slot s for k-chunk k0
    auto ldg_cvt_sts = [&](int s, int k0) {
        const float* p = xsrc + k0 + ah;
        float4 f0 = *reinterpret_cast<const float4*>(p + 0);
        float4 f1 = *reinterpret_cast<const float4*>(p + 4);
        float4 f2 = *reinterpret_cast<const float4*>(p + 8);
        float4 f3 = *reinterpret_cast<const float4*>(p + 12);
        uint4 h0 = make_uint4(pack_h2(f0.x, f0.y), pack_h2(f0.z, f0.w),
                              pack_h2(f1.x, f1.y), pack_h2(f1.z, f1.w));
        uint4 h1 = make_uint4(pack_h2(f2.x, f2.y), pack_h2(f2.z, f2.w),
                              pack_h2(f3.x, f3.y), pack_h2(f3.z, f3.w));
        char* dst = (char*)smA + s * 8192;
        *reinterpret_cast<uint4*>(dst + swz64((uint32_t)ar, (uint32_t)(ah * 2)))      = h0;
        *reinterpret_cast<uint4*>(dst + swz64((uint32_t)ar, (uint32_t)(ah * 2 + 16))) = h1;
    };

    // ---- prologue: B stages 0..2 async; A tiles 0,1 direct ----
    issueB(0, 0);      CP_COMMIT();
    issueB(1, BK);     CP_COMMIT();
    issueB(2, 2 * BK); CP_COMMIT();
    ldg_cvt_sts(0, 0);
    ldg_cvt_sts(1, BK);
    CP_WAIT2();                 // B tile 0 landed
    __syncthreads();

    for (int i = 0; i < NSTEP; i++) {
        const int cur = i % 3;

        // prefetch A tile i+2 into registers (hidden behind MMA below)
        float4 f0, f1, f2, f3;
        const bool hasA = (i + 2) < NSTEP;
        if (hasA) {
            const float* p = xsrc + (i + 2) * BK + ah;
            f0 = *reinterpret_cast<const float4*>(p + 0);
            f1 = *reinterpret_cast<const float4*>(p + 4);
            f2 = *reinterpret_cast<const float4*>(p + 8);
            f3 = *reinterpret_cast<const float4*>(p + 12);
        }

        // ---- MMA on A slot cur, B slot cur ----
        const uint32_t aBase = saBase + cur * 8192;
        const uint32_t bBase = sbBase + cur * 8192;
#pragma unroll
        for (int s = 0; s < 2; s++) {
            uint32_t af[4][4], bf[4][2];
#pragma unroll
            for (int mf = 0; mf < 4; mf++) {
                uint32_t a = aBase + swz64((uint32_t)(mBase + mf * 16 + (lane & 15)),
                                           (uint32_t)(s * 32 + ((lane >> 4) & 1) * 16));
                LDSM4(af[mf][0], af[mf][1], af[mf][2], af[mf][3], a);
            }
#pragma unroll
            for (int nf = 0; nf < 4; nf++) {
                uint32_t b = bBase + swz64((uint32_t)(nBase + nf * 8 + (lane & 7)),
                                           (uint32_t)(s * 32 + ((lane >> 3) & 1) * 16));
                LDSM2(bf[nf][0], bf[nf][1], b);
            }
#pragma unroll
            for (int mf = 0; mf < 4; mf++)
#pragma unroll
                for (int nf = 0; nf < 4; nf++)
                    MMA16816F16(acc[mf][nf], af[mf], bf[nf]);
        }

        // convert + store A tile i+2 into slot (i+2)%3 (read last at iter i-1)
        if (hasA) {
            uint4 h0 = make_uint4(pack_h2(f0.x, f0.y), pack_h2(f0.z, f0.w),
                                  pack_h2(f1.x, f1.y), pack_h2(f1.z, f1.w));
            uint4 h1 = make_uint4(pack_h2(f2.x, f2.y), pack_h2(f2.z, f2.w),
                                  pack_h2(f3.x, f3.y), pack_h2(f3.z, f3.w));
            char* dst = (char*)smA + ((i + 2) % 3) * 8192;
            *reinterpret_cast<uint4*>(dst + swz64((uint32_t)ar, (uint32_t)(ah * 2)))      = h0;
            *reinterpret_cast<uint4*>(dst + swz64((uint32_t)ar, (uint32_t)(ah * 2 + 16))) = h1;
        }
        __syncthreads();

        // refill B slot cur with tile i+3 (slot free: read this iter, now synced)
        if (i + 3 < NSTEP)
            issueB(cur, (i + 3) * BK);
        CP_COMMIT();                    // uniform group count per iter
        CP_WAIT2();                     // tile i+1 complete (2 newest may fly)
        __syncthreads();
    }

    // ---- epilogue: write support as fp16 ----
#pragma unroll
    for (int mf = 0; mf < 4; mf++) {
        int r0 = rowBase + mBase + mf * 16 + gid;
        int r1 = r0 + 8;
#pragma unroll
        for (int nf = 0; nf < 4; nf++) {
            int col = nBase + nf * 8 + tig * 2;
            if (r0 < M)
                *reinterpret_cast<uint32_t*>(&g_support_h[(size_t)r0 * D_OUT + col]) =
                    pack_h2(acc[mf][nf][0], acc[mf][nf][1]);
            if (r1 < M)
                *reinterpret_cast<uint32_t*>(&g_support_h[(size_t)r1 * D_OUT + col]) =
                    pack_h2(acc[mf][nf][2], acc[mf][nf][3]);
        }
    }
}

// ---------------------------------------------------------------------------
// Stage 2: rowptr[i] = lower_bound(edge_dst, i)
// ---------------------------------------------------------------------------
__global__ void rowptr_kernel(const int* __restrict__ edge_dst, int E, int M)
{
    int i = blockIdx.x * blockDim.x + threadIdx.x;
    if (i > M) return;
    int lo = 0, hi = E;
    while (lo < hi) {
        int mid = (lo + hi) >> 1;
        if (edge_dst[mid] < i) lo = mid + 1; else hi = mid;
    }
    g_rowptr[i] = lo;
}

// ---------------------------------------------------------------------------
// Stage 3: warp per node segment sum; fp16 gathers, unroll 8 (MLP=8)
// ---------------------------------------------------------------------------
__global__ __launch_bounds__(256)
void spmm_kernel(const int* __restrict__ edge_src,
                 const float* __restrict__ edge_val,
                 float* __restrict__ out, int M)
{
    const int warp = threadIdx.x >> 5;
    const int lane = threadIdx.x & 31;
    const int node = blockIdx.x * 8 + warp;
    if (node >= M) return;

    const int s = g_rowptr[node];
    const int e = g_rowptr[node + 1];

    float4 acc = make_float4(0.f, 0.f, 0.f, 0.f);
    float4 acc2 = make_float4(0.f, 0.f, 0.f, 0.f);
    const int col = lane * 4;
    const __half* supp = g_support_h;

    int i = s;
    for (; i + 7 < e; i += 8) {
        int   si[8]; float vi[8]; uint2 qi[8];
#pragma unroll
        for (int j = 0; j < 8; j++) si[j] = edge_src[i + j];
#pragma unroll
        for (int j = 0; j < 8; j++) vi[j] = edge_val[i + j];
#pragma unroll
        for (int j = 0; j < 8; j++)
            qi[j] = *reinterpret_cast<const uint2*>(&supp[(size_t)si[j] * D_OUT + col]);
#pragma unroll
        for (int j = 0; j < 8; j++) {
            float2 f0 = __half22float2(*reinterpret_cast<__half2*>(&qi[j].x));
            float2 f1 = __half22float2(*reinterpret_cast<__half2*>(&qi[j].y));
            if (j & 1) {
                acc2.x = fmaf(f0.x, vi[j], acc2.x); acc2.y = fmaf(f0.y, vi[j], acc2.y);
                acc2.z = fmaf(f1.x, vi[j], acc2.z); acc2.w = fmaf(f1.y, vi[j], acc2.w);
            } else {
                acc.x = fmaf(f0.x, vi[j], acc.x); acc.y = fmaf(f0.y, vi[j], acc.y);
                acc.z = fmaf(f1.x, vi[j], acc.z); acc.w = fmaf(f1.y, vi[j], acc.w);
            }
        }
    }
    for (; i < e; ++i) {
        int sr = edge_src[i];
        float v = edge_val[i];
        uint2 q = *reinterpret_cast<const uint2*>(&supp[(size_t)sr * D_OUT + col]);
        float2 f0 = __half22float2(*reinterpret_cast<__half2*>(&q.x));
        float2 f1 = __half22float2(*reinterpret_cast<__half2*>(&q.y));
        acc.x = fmaf(f0.x, v, acc.x); acc.y = fmaf(f0.y, v, acc.y);
        acc.z = fmaf(f1.x, v, acc.z); acc.w = fmaf(f1.y, v, acc.w);
    }
    acc.x += acc2.x; acc.y += acc2.y; acc.z += acc2.z; acc.w += acc2.w;

    *reinterpret_cast<float4*>(&out[(size_t)node * D_OUT + col]) = acc;
}

// ---------------------------------------------------------------------------
extern "C" void kernel_launch(void* const* d_in, const int* in_sizes, int n_in,
                              void* d_out, int out_size)
{
    const float* x        = (const float*)d_in[0];
    const int*   edge_src = (const int*)  d_in[1];
    const int*   edge_dst = (const int*)  d_in[2];
    const float* edge_val = (const float*)d_in[3];
    const float* weight   = (const float*)d_in[4];
    float*       out      = (float*)d_out;

    const int M = in_sizes[0] / D_IN;   // 50000
    const int E = in_sizes[1];          // 800000

    convw_kernel<<<(D_IN * D_OUT + 255) / 256, 256>>>(weight);
    rowptr_kernel<<<(M + 1 + 255) / 256, 256>>>(edge_dst, E, M);
    gemm_mma_kernel<<<(M + BM - 1) / BM, 256>>>(x, M);
    spmm_kernel<<<(M + 7) / 8, 256>>>(edge_src, edge_val, out, M);
}

// round 12
// speedup vs baseline: 1.1818x; 1.0591x over previous
#include <cuda_runtime.h>
#include <cuda_fp16.h>
#include <cstdint>

// ---------------------------------------------------------------------------
// GraphConvolution: out = segment_sum( (X@W)[edge_src] * edge_val, edge_dst )
// Stage 0: W f32 [k][n] -> fp16 transposed [n][k]
// Stage 1: GEMM mma.sync fp16 (round-9 fused cp.async f32 + in-smem convert)
// Stage 2: rowptr via binary search (edge_dst sorted)
// Stage 3: segment sum, 2 edges/warp-instruction (half-warp per edge, 16B gathers)
// ---------------------------------------------------------------------------

#define MAX_NODES 50000
#define D_IN      512
#define D_OUT     128
#define BK        32
#define NSTEP     (D_IN / BK)   // 16

// dynamic smem layout (bytes):
//   [0, 49152)        A f32 slots: 3 x 16384 (128 rows x 128B)
//   [49152, 73728)    B f16 slots: 3 x 8192  (128 rows x 64B)
//   [73728, 90112)    A f16 ping-pong: 2 x 8192
#define OFF_AF32  0
#define OFF_BF16  49152
#define OFF_AF16  73728
#define SMEM_DYN  90112

__device__ __align__(16) __half g_support_h[(size_t)MAX_NODES * D_OUT];
__device__ int   g_rowptr[MAX_NODES + 1];
__device__ __align__(16) __half g_Wh[D_OUT * D_IN];            // [n][k]

// ------------------------------- helpers -----------------------------------
__device__ __forceinline__ uint32_t smem_u32(const void* p) {
    uint32_t a;
    asm("{ .reg .u64 t; cvta.to.shared.u64 t, %1; cvt.u32.u64 %0, t; }"
        : "=r"(a) : "l"(p));
    return a;
}
__device__ __forceinline__ uint32_t swz64(uint32_t r, uint32_t c) {
    return r * 64 + ((((c >> 4) ^ (r >> 1)) & 3u) << 4) + (c & 15u);
}
__device__ __forceinline__ uint32_t swzf32(uint32_t r, uint32_t c) {
    return r * 128 + ((((c >> 4) ^ r) & 7u) << 4) + (c & 15u);
}

#define CP_ASYNC16(dst, src) \
    asm volatile("cp.async.cg.shared.global [%0], [%1], 16;" \
        :: "r"(dst), "l"(src) : "memory")
#define CP_COMMIT() asm volatile("cp.async.commit_group;" ::: "memory")
#define CP_WAIT1()  asm volatile("cp.async.wait_group 1;" ::: "memory")
#define CP_WAIT2()  asm volatile("cp.async.wait_group 2;" ::: "memory")

#define LDSM4(r0, r1, r2, r3, a) \
    asm volatile("ldmatrix.sync.aligned.m8n8.x4.shared.b16 {%0,%1,%2,%3}, [%4];" \
        : "=r"(r0), "=r"(r1), "=r"(r2), "=r"(r3) : "r"(a))
#define LDSM2(r0, r1, a) \
    asm volatile("ldmatrix.sync.aligned.m8n8.x2.shared.b16 {%0,%1}, [%2];" \
        : "=r"(r0), "=r"(r1) : "r"(a))
#define MMA16816F16(c, a, b) \
    asm volatile("mma.sync.aligned.m16n8k16.row.col.f32.f16.f16.f32 " \
        "{%0,%1,%2,%3}, {%4,%5,%6,%7}, {%8,%9}, {%0,%1,%2,%3};" \
        : "+f"((c)[0]), "+f"((c)[1]), "+f"((c)[2]), "+f"((c)[3]) \
        : "r"((a)[0]), "r"((a)[1]), "r"((a)[2]), "r"((a)[3]), \
          "r"((b)[0]), "r"((b)[1]))

__device__ __forceinline__ uint32_t pack_h2(float lo, float hi) {
    __half2 h = __float22half2_rn(make_float2(lo, hi));
    return *reinterpret_cast<uint32_t*>(&h);
}

// ---------------------------------------------------------------------------
// Stage 0: convert + transpose W -> fp16 [n][k]
// ---------------------------------------------------------------------------
__global__ void convw_kernel(const float* __restrict__ W)
{
    int idx = blockIdx.x * blockDim.x + threadIdx.x;
    if (idx >= D_IN * D_OUT) return;
    int k = idx >> 7;
    int n = idx & 127;
    g_Wh[n * D_IN + k] = __float2half_rn(W[idx]);
}

// ---------------------------------------------------------------------------
// Stage 1: GEMM (round-9 fused pipeline, verbatim)
// ---------------------------------------------------------------------------
__global__ __launch_bounds__(256, 2)
void gemm_mma_kernel(const float* __restrict__ X, int M)
{
    extern __shared__ char dyn[];
    const uint32_t sb = smem_u32(dyn);

    const int tid  = threadIdx.x;
    const int w    = tid >> 5;
    const int lane = tid & 31;
    const int gid  = lane >> 2;
    const int tig  = lane & 3;
    const int rowBase = blockIdx.x * 128;
    const int mBase = (w >> 2) * 64;
    const int nBase = (w & 3) * 32;

    float acc[4][4][4];
#pragma unroll
    for (int i = 0; i < 4; i++)
#pragma unroll
        for (int j = 0; j < 4; j++)
#pragma unroll
            for (int q = 0; q < 4; q++) acc[i][j][q] = 0.f;

    const int ar   = tid >> 1;
    const int aseg = (tid & 1) * 64;
    const int bc   = (tid & 1) * 32;
    const float*  xsrc = X + (size_t)(rowBase + ar < M ? rowBase + ar : M - 1) * D_IN;
    const __half* wsrc = g_Wh + (size_t)ar * D_IN;

    auto issue_stage = [&](int s, int k0) {
        uint32_t aB = sb + OFF_AF32 + s * 16384;
        uint32_t bB = sb + OFF_BF16 + s * 8192;
#pragma unroll
        for (int j = 0; j < 4; j++) {
            int c = aseg + j * 16;
            CP_ASYNC16(aB + swzf32((uint32_t)ar, (uint32_t)c), xsrc + k0 + c / 4);
        }
        CP_ASYNC16(bB + swz64((uint32_t)ar, (uint32_t)bc),        wsrc + k0 + bc / 2);
        CP_ASYNC16(bB + swz64((uint32_t)ar, (uint32_t)(bc + 16)), wsrc + k0 + bc / 2 + 8);
    };

    auto convert_stage = [&](int s, int p) {
        const char* src = dyn + OFF_AF32 + s * 16384;
        char*       dst = dyn + OFF_AF16 + p * 8192;
        float4 f0 = *reinterpret_cast<const float4*>(src + swzf32((uint32_t)ar, (uint32_t)(aseg)));
        float4 f1 = *reinterpret_cast<const float4*>(src + swzf32((uint32_t)ar, (uint32_t)(aseg + 16)));
        float4 f2 = *reinterpret_cast<const float4*>(src + swzf32((uint32_t)ar, (uint32_t)(aseg + 32)));
        float4 f3 = *reinterpret_cast<const float4*>(src + swzf32((uint32_t)ar, (uint32_t)(aseg + 48)));
        uint4 h0 = make_uint4(pack_h2(f0.x, f0.y), pack_h2(f0.z, f0.w),
                              pack_h2(f1.x, f1.y), pack_h2(f1.z, f1.w));
        uint4 h1 = make_uint4(pack_h2(f2.x, f2.y), pack_h2(f2.z, f2.w),
                              pack_h2(f3.x, f3.y), pack_h2(f3.z, f3.w));
        *reinterpret_cast<uint4*>(dst + swz64((uint32_t)ar, (uint32_t)(aseg / 2)))      = h0;
        *reinterpret_cast<uint4*>(dst + swz64((uint32_t)ar, (uint32_t)(aseg / 2 + 16))) = h1;
    };

    issue_stage(0, 0);       CP_COMMIT();
    issue_stage(1, BK);      CP_COMMIT();
    issue_stage(2, 2 * BK);  CP_COMMIT();
    CP_WAIT2();
    __syncthreads();
    convert_stage(0, 0);
    __syncthreads();

    for (int i = 0; i < NSTEP; i++) {
        const int cur = i % 3;
        const int pp  = i & 1;

        if (i + 1 < NSTEP) {
            CP_WAIT1();
            __syncthreads();
            convert_stage((i + 1) % 3, pp ^ 1);
        }

        const uint32_t aBase = sb + OFF_AF16 + pp * 8192;
        const uint32_t bBase = sb + OFF_BF16 + cur * 8192;
#pragma unroll
        for (int s = 0; s < 2; s++) {
            uint32_t af[4][4], bf[4][2];
#pragma unroll
            for (int mf = 0; mf < 4; mf++) {
                uint32_t a = aBase + swz64((uint32_t)(mBase + mf * 16 + (lane & 15)),
                                           (uint32_t)(s * 32 + ((lane >> 4) & 1) * 16));
                LDSM4(af[mf][0], af[mf][1], af[mf][2], af[mf][3], a);
            }
#pragma unroll
            for (int nf = 0; nf < 4; nf++) {
                uint32_t b = bBase + swz64((uint32_t)(nBase + nf * 8 + (lane & 7)),
                                           (uint32_t)(s * 32 + ((lane >> 3) & 1) * 16));
                LDSM2(bf[nf][0], bf[nf][1], b);
            }
#pragma unroll
            for (int mf = 0; mf < 4; mf++)
#pragma unroll
                for (int nf = 0; nf < 4; nf++)
                    MMA16816F16(acc[mf][nf], af[mf], bf[nf]);
        }
        __syncthreads();

        if (i + 3 < NSTEP)
            issue_stage(cur, (i + 3) * BK);
        CP_COMMIT();
    }

#pragma unroll
    for (int mf = 0; mf < 4; mf++) {
        int r0 = rowBase + mBase + mf * 16 + gid;
        int r1 = r0 + 8;
#pragma unroll
        for (int nf = 0; nf < 4; nf++) {
            int col = nBase + nf * 8 + tig * 2;
            if (r0 < M)
                *reinterpret_cast<uint32_t*>(&g_support_h[(size_t)r0 * D_OUT + col]) =
                    pack_h2(acc[mf][nf][0], acc[mf][nf][1]);
            if (r1 < M)
                *reinterpret_cast<uint32_t*>(&g_support_h[(size_t)r1 * D_OUT + col]) =
                    pack_h2(acc[mf][nf][2], acc[mf][nf][3]);
        }
    }
}

// ---------------------------------------------------------------------------
// Stage 2: rowptr[i] = lower_bound(edge_dst, i)
// ---------------------------------------------------------------------------
__global__ void rowptr_kernel(const int* __restrict__ edge_dst, int E, int M)
{
    int i = blockIdx.x * blockDim.x + threadIdx.x;
    if (i > M) return;
    int lo = 0, hi = E;
    while (lo < hi) {
        int mid = (lo + hi) >> 1;
        if (edge_dst[mid] < i) lo = mid + 1; else hi = mid;
    }
    g_rowptr[i] = lo;
}

// ---------------------------------------------------------------------------
// Stage 3: warp per node, 2 edges per warp-instruction:
//   lanes 0-15 process even edges, lanes 16-31 odd edges; each lane gathers
//   16B (8 fp16 cols). Cross-half shuffle reduce at the end.
// ---------------------------------------------------------------------------
__device__ __forceinline__ void fma8(float* acc, uint4 q, float v) {
    float2 f0 = __half22float2(*reinterpret_cast<__half2*>(&q.x));
    float2 f1 = __half22float2(*reinterpret_cast<__half2*>(&q.y));
    float2 f2 = __half22float2(*reinterpret_cast<__half2*>(&q.z));
    float2 f3 = __half22float2(*reinterpret_cast<__half2*>(&q.w));
    acc[0] = fmaf(f0.x, v, acc[0]); acc[1] = fmaf(f0.y, v, acc[1]);
    acc[2] = fmaf(f1.x, v, acc[2]); acc[3] = fmaf(f1.y, v, acc[3]);
    acc[4] = fmaf(f2.x, v, acc[4]); acc[5] = fmaf(f2.y, v, acc[5]);
    acc[6] = fmaf(f3.x, v, acc[6]); acc[7] = fmaf(f3.y, v, acc[7]);
}

__global__ __launch_bounds__(256)
void spmm_kernel(const int* __restrict__ edge_src,
                 const float* __restrict__ edge_val,
                 float* __restrict__ out, int M)
{
    const int warp = threadIdx.x >> 5;
    const int lane = threadIdx.x & 31;
    const int node = blockIdx.x * 8 + warp;
    if (node >= M) return;

    const int s = g_rowptr[node];
    const int e = g_rowptr[node + 1];
    const int half = lane >> 4;          // 0: even edges, 1: odd edges
    const int col  = (lane & 15) * 8;    // 8 fp16 columns per lane
    const __half* supp = g_support_h + col;

    float acc[8];
#pragma unroll
    for (int j = 0; j < 8; j++) acc[j] = 0.f;

    int i = s + half;
    // 4 pairs in flight per lane (8 edges per warp per unrolled step)
    for (; i + 6 < e; i += 8) {
        int   s0 = edge_src[i],     s1 = edge_src[i + 2];
        int   s2 = edge_src[i + 4], s3 = edge_src[i + 6];
        float v0 = edge_val[i],     v1 = edge_val[i + 2];
        float v2 = edge_val[i + 4], v3 = edge_val[i + 6];
        uint4 q0 = *reinterpret_cast<const uint4*>(&supp[(size_t)s0 * D_OUT]);
        uint4 q1 = *reinterpret_cast<const uint4*>(&supp[(size_t)s1 * D_OUT]);
        uint4 q2 = *reinterpret_cast<const uint4*>(&supp[(size_t)s2 * D_OUT]);
        uint4 q3 = *reinterpret_cast<const uint4*>(&supp[(size_t)s3 * D_OUT]);
        fma8(acc, q0, v0);
        fma8(acc, q1, v1);
        fma8(acc, q2, v2);
        fma8(acc, q3, v3);
    }
    for (; i < e; i += 2) {
        int   sr = edge_src[i];
        float v  = edge_val[i];
        uint4 q  = *reinterpret_cast<const uint4*>(&supp[(size_t)sr * D_OUT]);
        fma8(acc, q, v);
    }

    // combine even/odd halves: lane L (half 0) += lane L+16 (half 1)
#pragma unroll
    for (int j = 0; j < 8; j++)
        acc[j] += __shfl_xor_sync(0xFFFFFFFFu, acc[j], 16);

    if (half == 0) {
        float* dst = &out[(size_t)node * D_OUT + col];
        *reinterpret_cast<float4*>(dst)     = make_float4(acc[0], acc[1], acc[2], acc[3]);
        *reinterpret_cast<float4*>(dst + 4) = make_float4(acc[4], acc[5], acc[6], acc[7]);
    }
}

// ---------------------------------------------------------------------------
extern "C" void kernel_launch(void* const* d_in, const int* in_sizes, int n_in,
                              void* d_out, int out_size)
{
    const float* x        = (const float*)d_in[0];
    const int*   edge_src = (const int*)  d_in[1];
    const int*   edge_dst = (const int*)  d_in[2];
    const float* edge_val = (const float*)d_in[3];
    const float* weight   = (const float*)d_in[4];
    float*       out      = (float*)d_out;

    const int M = in_sizes[0] / D_IN;   // 50000
    const int E = in_sizes[1];          // 800000

    cudaFuncSetAttribute(gemm_mma_kernel,
                         cudaFuncAttributeMaxDynamicSharedMemorySize, SMEM_DYN);

    convw_kernel<<<(D_IN * D_OUT + 255) / 256, 256>>>(weight);
    rowptr_kernel<<<(M + 1 + 255) / 256, 256>>>(edge_dst, E, M);
    gemm_mma_kernel<<<(M + 127) / 128, 256, SMEM_DYN>>>(x, M);
    spmm_kernel<<<(M + 7) / 8, 256>>>(edge_src, edge_val, out, M);
}

// round 13
// speedup vs baseline: 1.1875x; 1.0048x over previous
#include <cuda_runtime.h>
#include <cuda_fp16.h>
#include <cstdint>

// ---------------------------------------------------------------------------
// GraphConvolution: out = segment_sum( (X@W)[edge_src] * edge_val, edge_dst )
// Stage 0: W f32 [k][n] -> fp16 transposed [n][k]
// Stage 1: GEMM mma.sync fp16, cp.async f32 A + in-smem convert,
//          convert scheduled BETWEEN the two MMA sub-steps (latency overlap)
// Stage 2: rowptr via binary search (edge_dst sorted)
// Stage 3: warp-per-node segment sum, fp16 gathers, unroll 8 (round-11 best)
// ---------------------------------------------------------------------------

#define MAX_NODES 50000
#define D_IN      512
#define D_OUT     128
#define BK        32
#define NSTEP     (D_IN / BK)   // 16

// dynamic smem layout (bytes):
//   [0, 49152)        A f32 slots: 3 x 16384 (128 rows x 128B)
//   [49152, 73728)    B f16 slots: 3 x 8192  (128 rows x 64B)
//   [73728, 90112)    A f16 ping-pong: 2 x 8192
#define OFF_AF32  0
#define OFF_BF16  49152
#define OFF_AF16  73728
#define SMEM_DYN  90112

__device__ __align__(16) __half g_support_h[(size_t)MAX_NODES * D_OUT];
__device__ int   g_rowptr[MAX_NODES + 1];
__device__ __align__(16) __half g_Wh[D_OUT * D_IN];            // [n][k]

// ------------------------------- helpers -----------------------------------
__device__ __forceinline__ uint32_t smem_u32(const void* p) {
    uint32_t a;
    asm("{ .reg .u64 t; cvta.to.shared.u64 t, %1; cvt.u32.u64 %0, t; }"
        : "=r"(a) : "l"(p));
    return a;
}
__device__ __forceinline__ uint32_t swz64(uint32_t r, uint32_t c) {
    return r * 64 + ((((c >> 4) ^ (r >> 1)) & 3u) << 4) + (c & 15u);
}
__device__ __forceinline__ uint32_t swzf32(uint32_t r, uint32_t c) {
    return r * 128 + ((((c >> 4) ^ r) & 7u) << 4) + (c & 15u);
}

#define CP_ASYNC16(dst, src) \
    asm volatile("cp.async.cg.shared.global [%0], [%1], 16;" \
        :: "r"(dst), "l"(src) : "memory")
#define CP_COMMIT() asm volatile("cp.async.commit_group;" ::: "memory")
#define CP_WAIT1()  asm volatile("cp.async.wait_group 1;" ::: "memory")
#define CP_WAIT2()  asm volatile("cp.async.wait_group 2;" ::: "memory")

#define LDSM4(r0, r1, r2, r3, a) \
    asm volatile("ldmatrix.sync.aligned.m8n8.x4.shared.b16 {%0,%1,%2,%3}, [%4];" \
        : "=r"(r0), "=r"(r1), "=r"(r2), "=r"(r3) : "r"(a))
#define LDSM2(r0, r1, a) \
    asm volatile("ldmatrix.sync.aligned.m8n8.x2.shared.b16 {%0,%1}, [%2];" \
        : "=r"(r0), "=r"(r1) : "r"(a))
#define MMA16816F16(c, a, b) \
    asm volatile("mma.sync.aligned.m16n8k16.row.col.f32.f16.f16.f32 " \
        "{%0,%1,%2,%3}, {%4,%5,%6,%7}, {%8,%9}, {%0,%1,%2,%3};" \
        : "+f"((c)[0]), "+f"((c)[1]), "+f"((c)[2]), "+f"((c)[3]) \
        : "r"((a)[0]), "r"((a)[1]), "r"((a)[2]), "r"((a)[3]), \
          "r"((b)[0]), "r"((b)[1]))

__device__ __forceinline__ uint32_t pack_h2(float lo, float hi) {
    __half2 h = __float22half2_rn(make_float2(lo, hi));
    return *reinterpret_cast<uint32_t*>(&h);
}

// ---------------------------------------------------------------------------
// Stage 0: convert + transpose W -> fp16 [n][k]
// ---------------------------------------------------------------------------
__global__ void convw_kernel(const float* __restrict__ W)
{
    int idx = blockIdx.x * blockDim.x + threadIdx.x;
    if (idx >= D_IN * D_OUT) return;
    int k = idx >> 7;
    int n = idx & 127;
    g_Wh[n * D_IN + k] = __float2half_rn(W[idx]);
}

// ---------------------------------------------------------------------------
// Stage 1: GEMM; 128x128 tile, 256 threads, convert interleaved with MMA
// ---------------------------------------------------------------------------
__global__ __launch_bounds__(256, 2)
void gemm_mma_kernel(const float* __restrict__ X, int M)
{
    extern __shared__ char dyn[];
    const uint32_t sb = smem_u32(dyn);

    const int tid  = threadIdx.x;
    const int w    = tid >> 5;
    const int lane = tid & 31;
    const int gid  = lane >> 2;
    const int tig  = lane & 3;
    const int rowBase = blockIdx.x * 128;
    const int mBase = (w >> 2) * 64;
    const int nBase = (w & 3) * 32;

    float acc[4][4][4];
#pragma unroll
    for (int i = 0; i < 4; i++)
#pragma unroll
        for (int j = 0; j < 4; j++)
#pragma unroll
            for (int q = 0; q < 4; q++) acc[i][j][q] = 0.f;

    const int ar   = tid >> 1;
    const int aseg = (tid & 1) * 64;
    const int bc   = (tid & 1) * 32;
    const float*  xsrc = X + (size_t)(rowBase + ar < M ? rowBase + ar : M - 1) * D_IN;
    const __half* wsrc = g_Wh + (size_t)ar * D_IN;

    auto issue_stage = [&](int s, int k0) {
        uint32_t aB = sb + OFF_AF32 + s * 16384;
        uint32_t bB = sb + OFF_BF16 + s * 8192;
#pragma unroll
        for (int j = 0; j < 4; j++) {
            int c = aseg + j * 16;
            CP_ASYNC16(aB + swzf32((uint32_t)ar, (uint32_t)c), xsrc + k0 + c / 4);
        }
        CP_ASYNC16(bB + swz64((uint32_t)ar, (uint32_t)bc),        wsrc + k0 + bc / 2);
        CP_ASYNC16(bB + swz64((uint32_t)ar, (uint32_t)(bc + 16)), wsrc + k0 + bc / 2 + 8);
    };

    auto convert_stage = [&](int s, int p) {
        const char* src = dyn + OFF_AF32 + s * 16384;
        char*       dst = dyn + OFF_AF16 + p * 8192;
        float4 f0 = *reinterpret_cast<const float4*>(src + swzf32((uint32_t)ar, (uint32_t)(aseg)));
        float4 f1 = *reinterpret_cast<const float4*>(src + swzf32((uint32_t)ar, (uint32_t)(aseg + 16)));
        float4 f2 = *reinterpret_cast<const float4*>(src + swzf32((uint32_t)ar, (uint32_t)(aseg + 32)));
        float4 f3 = *reinterpret_cast<const float4*>(src + swzf32((uint32_t)ar, (uint32_t)(aseg + 48)));
        uint4 h0 = make_uint4(pack_h2(f0.x, f0.y), pack_h2(f0.z, f0.w),
                              pack_h2(f1.x, f1.y), pack_h2(f1.z, f1.w));
        uint4 h1 = make_uint4(pack_h2(f2.x, f2.y), pack_h2(f2.z, f2.w),
                              pack_h2(f3.x, f3.y), pack_h2(f3.z, f3.w));
        *reinterpret_cast<uint4*>(dst + swz64((uint32_t)ar, (uint32_t)(aseg / 2)))      = h0;
        *reinterpret_cast<uint4*>(dst + swz64((uint32_t)ar, (uint32_t)(aseg / 2 + 16))) = h1;
    };

    // one MMA sub-step (s = 0 or 1) on fp16 A buffer p, B slot cur
    auto mma_substep = [&](int p, int cur, int s) {
        const uint32_t aBase = sb + OFF_AF16 + p * 8192;
        const uint32_t bBase = sb + OFF_BF16 + cur * 8192;
        uint32_t af[4][4], bf[4][2];
#pragma unroll
        for (int mf = 0; mf < 4; mf++) {
            uint32_t a = aBase + swz64((uint32_t)(mBase + mf * 16 + (lane & 15)),
                                       (uint32_t)(s * 32 + ((lane >> 4) & 1) * 16));
            LDSM4(af[mf][0], af[mf][1], af[mf][2], af[mf][3], a);
        }
#pragma unroll
        for (int nf = 0; nf < 4; nf++) {
            uint32_t b = bBase + swz64((uint32_t)(nBase + nf * 8 + (lane & 7)),
                                       (uint32_t)(s * 32 + ((lane >> 3) & 1) * 16));
            LDSM2(bf[nf][0], bf[nf][1], b);
        }
#pragma unroll
        for (int mf = 0; mf < 4; mf++)
#pragma unroll
            for (int nf = 0; nf < 4; nf++)
                MMA16816F16(acc[mf][nf], af[mf], bf[nf]);
    };

    // ---- prologue: tiles 0,1,2 in flight; convert tile 0 ----
    issue_stage(0, 0);       CP_COMMIT();
    issue_stage(1, BK);      CP_COMMIT();
    issue_stage(2, 2 * BK);  CP_COMMIT();
    CP_WAIT2();
    __syncthreads();
    convert_stage(0, 0);
    __syncthreads();

    for (int i = 0; i < NSTEP; i++) {
        const int cur = i % 3;
        const int pp  = i & 1;

        if (i + 1 < NSTEP) {
            CP_WAIT1();          // tiles <= i+1 landed
            __syncthreads();
        }

        // sub-step 0 first: warp issues MMAs before convert's LDS chain
        mma_substep(pp, cur, 0);
        // convert tile i+1 (independent of this iter's MMAs; its latency
        // drains under sub-step 1's tensor work)
        if (i + 1 < NSTEP)
            convert_stage((i + 1) % 3, pp ^ 1);
        mma_substep(pp, cur, 1);

        __syncthreads();

        if (i + 3 < NSTEP)
            issue_stage(cur, (i + 3) * BK);
        CP_COMMIT();
    }

    // ---- epilogue: write support as fp16 ----
#pragma unroll
    for (int mf = 0; mf < 4; mf++) {
        int r0 = rowBase + mBase + mf * 16 + gid;
        int r1 = r0 + 8;
#pragma unroll
        for (int nf = 0; nf < 4; nf++) {
            int col = nBase + nf * 8 + tig * 2;
            if (r0 < M)
                *reinterpret_cast<uint32_t*>(&g_support_h[(size_t)r0 * D_OUT + col]) =
                    pack_h2(acc[mf][nf][0], acc[mf][nf][1]);
            if (r1 < M)
                *reinterpret_cast<uint32_t*>(&g_support_h[(size_t)r1 * D_OUT + col]) =
                    pack_h2(acc[mf][nf][2], acc[mf][nf][3]);
        }
    }
}

// ---------------------------------------------------------------------------
// Stage 2: rowptr[i] = lower_bound(edge_dst, i)
// ---------------------------------------------------------------------------
__global__ void rowptr_kernel(const int* __restrict__ edge_dst, int E, int M)
{
    int i = blockIdx.x * blockDim.x + threadIdx.x;
    if (i > M) return;
    int lo = 0, hi = E;
    while (lo < hi) {
        int mid = (lo + hi) >> 1;
        if (edge_dst[mid] < i) lo = mid + 1; else hi = mid;
    }
    g_rowptr[i] = lo;
}

// ---------------------------------------------------------------------------
// Stage 3: warp per node segment sum; fp16 gathers, unroll 8 (round-11 best)
// ---------------------------------------------------------------------------
__global__ __launch_bounds__(256)
void spmm_kernel(const int* __restrict__ edge_src,
                 const float* __restrict__ edge_val,
                 float* __restrict__ out, int M)
{
    const int warp = threadIdx.x >> 5;
    const int lane = threadIdx.x & 31;
    const int node = blockIdx.x * 8 + warp;
    if (node >= M) return;

    const int s = g_rowptr[node];
    const int e = g_rowptr[node + 1];

    float4 acc = make_float4(0.f, 0.f, 0.f, 0.f);
    float4 acc2 = make_float4(0.f, 0.f, 0.f, 0.f);
    const int col = lane * 4;
    const __half* supp = g_support_h;

    int i = s;
    for (; i + 7 < e; i += 8) {
        int   si[8]; float vi[8]; uint2 qi[8];
#pragma unroll
        for (int j = 0; j < 8; j++) si[j] = edge_src[i + j];
#pragma unroll
        for (int j = 0; j < 8; j++) vi[j] = edge_val[i + j];
#pragma unroll
        for (int j = 0; j < 8; j++)
            qi[j] = *reinterpret_cast<const uint2*>(&supp[(size_t)si[j] * D_OUT + col]);
#pragma unroll
        for (int j = 0; j < 8; j++) {
            float2 f0 = __half22float2(*reinterpret_cast<__half2*>(&qi[j].x));
            float2 f1 = __half22float2(*reinterpret_cast<__half2*>(&qi[j].y));
            if (j & 1) {
                acc2.x = fmaf(f0.x, vi[j], acc2.x); acc2.y = fmaf(f0.y, vi[j], acc2.y);
                acc2.z = fmaf(f1.x, vi[j], acc2.z); acc2.w = fmaf(f1.y, vi[j], acc2.w);
            } else {
                acc.x = fmaf(f0.x, vi[j], acc.x); acc.y = fmaf(f0.y, vi[j], acc.y);
                acc.z = fmaf(f1.x, vi[j], acc.z); acc.w = fmaf(f1.y, vi[j], acc.w);
            }
        }
    }
    for (; i < e; ++i) {
        int sr = edge_src[i];
        float v = edge_val[i];
        uint2 q = *reinterpret_cast<const uint2*>(&supp[(size_t)sr * D_OUT + col]);
        float2 f0 = __half22float2(*reinterpret_cast<__half2*>(&q.x));
        float2 f1 = __half22float2(*reinterpret_cast<__half2*>(&q.y));
        acc.x = fmaf(f0.x, v, acc.x); acc.y = fmaf(f0.y, v, acc.y);
        acc.z = fmaf(f1.x, v, acc.z); acc.w = fmaf(f1.y, v, acc.w);
    }
    acc.x += acc2.x; acc.y += acc2.y; acc.z += acc2.z; acc.w += acc2.w;

    *reinterpret_cast<float4*>(&out[(size_t)node * D_OUT + col]) = acc;
}

// ---------------------------------------------------------------------------
extern "C" void kernel_launch(void* const* d_in, const int* in_sizes, int n_in,
                              void* d_out, int out_size)
{
    const float* x        = (const float*)d_in[0];
    const int*   edge_src = (const int*)  d_in[1];
    const int*   edge_dst = (const int*)  d_in[2];
    const float* edge_val = (const float*)d_in[3];
    const float* weight   = (const float*)d_in[4];
    float*       out      = (float*)d_out;

    const int M = in_sizes[0] / D_IN;   // 50000
    const int E = in_sizes[1];          // 800000

    cudaFuncSetAttribute(gemm_mma_kernel,
                         cudaFuncAttributeMaxDynamicSharedMemorySize, SMEM_DYN);

    convw_kernel<<<(D_IN * D_OUT + 255) / 256, 256>>>(weight);
    rowptr_kernel<<<(M + 1 + 255) / 256, 256>>>(edge_dst, E, M);
    gemm_mma_kernel<<<(M + 127) / 128, 256, SMEM_DYN>>>(x, M);
    spmm_kernel<<<(M + 7) / 8, 256>>>(edge_src, edge_val, out, M);
}